// round 2
// baseline (speedup 1.0000x reference)
#include <cuda_runtime.h>
#include <cstdint>

#define N_NODES 100000
#define D_FEAT 64
#define H_DIM 128

// Scratch: flow_total [N, 64] + dtype flag. Static device globals (no allocs).
__device__ float g_flow[N_NODES * D_FEAT];
__device__ int g_is64;

// ---------------------------------------------------------------------------
// Detect whether edge_index is int64 (all high words of first 512 entries are
// zero, since values are in [0, 100000)) or int32.
// ---------------------------------------------------------------------------
__global__ void detect_kernel(const int* __restrict__ ei) {
    if (threadIdx.x == 0 && blockIdx.x == 0) {
        int ok = 1;
        for (int i = 0; i < 512; ++i) {
            if (ei[2 * i + 1] != 0) { ok = 0; break; }
        }
        g_is64 = ok;
    }
}

__global__ void zero_kernel() {
    int i = blockIdx.x * blockDim.x + threadIdx.x;
    const int n = (N_NODES * D_FEAT) / 4;
    if (i < n) {
        reinterpret_cast<float4*>(g_flow)[i] = make_float4(0.f, 0.f, 0.f, 0.f);
    }
}

// ---------------------------------------------------------------------------
// Scatter: each edge's 64-float feature is added into flow[past] and
// flow[future]. 16 threads per edge, one float4 each, red.global.add.v4.f32.
// ---------------------------------------------------------------------------
__global__ void scatter_kernel(const float4* __restrict__ ea,
                               const void* __restrict__ eidx, int E) {
    long long tid = (long long)blockIdx.x * blockDim.x + threadIdx.x;
    int e = (int)(tid >> 4);
    int q = (int)(tid & 15);
    if (e >= E) return;

    long long a, b;
    if (g_is64) {
        const long long* x = (const long long*)eidx;
        a = x[e];
        b = x[E + e];
    } else {
        const int* x = (const int*)eidx;
        a = (long long)x[e];
        b = (long long)x[E + e];
    }

    float4 v = ea[(long long)e * 16 + q];
    float* p0 = &g_flow[a * 64 + q * 4];
    float* p1 = &g_flow[b * 64 + q * 4];
    asm volatile("red.global.add.v4.f32 [%0], {%1,%2,%3,%4};"
                 :: "l"(p0), "f"(v.x), "f"(v.y), "f"(v.z), "f"(v.w) : "memory");
    asm volatile("red.global.add.v4.f32 [%0], {%1,%2,%3,%4};"
                 :: "l"(p1), "f"(v.x), "f"(v.y), "f"(v.z), "f"(v.w) : "memory");
}

// ---------------------------------------------------------------------------
// Fused MLP: out = relu(flow @ W1 + b1) @ W2 + b2.
// One node per thread; W1/W2/b1/b2 in SMEM (warp-broadcast reads); flow and
// output staged through transposed SMEM for coalesced global access.
// Dynamic SMEM layout (floats):
//   sW1 [64*128] | sW2 [128*64] | sb1 [128] | sb2 [64] | sF [64][257]
// ---------------------------------------------------------------------------
__global__ __launch_bounds__(256, 1) void mlp_kernel(
    const float* __restrict__ W1, const float* __restrict__ b1,
    const float* __restrict__ W2, const float* __restrict__ b2,
    float* __restrict__ out) {
    extern __shared__ float sm[];
    float* sW1 = sm;           // 8192
    float* sW2 = sm + 8192;    // 8192
    float* sb1 = sm + 16384;   // 128
    float* sb2 = sm + 16512;   // 64
    float* sF  = sm + 16576;   // 64 * 257

    const int tid = threadIdx.x;
    const int node0 = blockIdx.x * 256;
    const int nNodes = min(256, N_NODES - node0);

    #pragma unroll 4
    for (int i = tid; i < 8192; i += 256) sW1[i] = W1[i];
    #pragma unroll 4
    for (int i = tid; i < 8192; i += 256) sW2[i] = W2[i];
    if (tid < 128) sb1[tid] = b1[tid];
    if (tid < 64)  sb2[tid] = b2[tid];
    // Coalesced load of flow tile, stored transposed: sF[d][n]
    for (int i = tid; i < nNodes * 64; i += 256) {
        int n = i >> 6, d = i & 63;
        sF[d * 257 + n] = g_flow[(long long)(node0 + n) * 64 + d];
    }
    __syncthreads();

    const bool active = (tid < nNodes);
    float fl[64];
    #pragma unroll
    for (int d = 0; d < 64; ++d) fl[d] = active ? sF[d * 257 + tid] : 0.f;

    float acc[64];
    #pragma unroll
    for (int o = 0; o < 64; ++o) acc[o] = 0.f;

    for (int j = 0; j < 128; j += 4) {
        float h0 = sb1[j], h1 = sb1[j + 1], h2 = sb1[j + 2], h3 = sb1[j + 3];
        #pragma unroll
        for (int d = 0; d < 64; ++d) {
            float fd = fl[d];
            float4 w = *reinterpret_cast<const float4*>(&sW1[d * 128 + j]);
            h0 = fmaf(fd, w.x, h0);
            h1 = fmaf(fd, w.y, h1);
            h2 = fmaf(fd, w.z, h2);
            h3 = fmaf(fd, w.w, h3);
        }
        h0 = fmaxf(h0, 0.f);
        h1 = fmaxf(h1, 0.f);
        h2 = fmaxf(h2, 0.f);
        h3 = fmaxf(h3, 0.f);
        float hv[4] = {h0, h1, h2, h3};
        #pragma unroll
        for (int k = 0; k < 4; ++k) {
            float hk = hv[k];
            const float* w2r = &sW2[(j + k) * 64];
            #pragma unroll
            for (int o = 0; o < 64; o += 4) {
                float4 w = *reinterpret_cast<const float4*>(&w2r[o]);
                acc[o]     = fmaf(hk, w.x, acc[o]);
                acc[o + 1] = fmaf(hk, w.y, acc[o + 1]);
                acc[o + 2] = fmaf(hk, w.z, acc[o + 2]);
                acc[o + 3] = fmaf(hk, w.w, acc[o + 3]);
            }
        }
    }

    // Each thread writes only its own column of sF (no cross-thread hazard
    // with the compute phase), then one barrier before the coalesced store.
    if (active) {
        #pragma unroll
        for (int o = 0; o < 64; ++o) sF[o * 257 + tid] = acc[o] + sb2[o];
    }
    __syncthreads();
    for (int i = tid; i < nNodes * 64; i += 256) {
        int n = i >> 6, d = i & 63;
        out[(long long)(node0 + n) * 64 + d] = sF[d * 257 + n];
    }
}

// ---------------------------------------------------------------------------
// Launch
// ---------------------------------------------------------------------------
extern "C" void kernel_launch(void* const* d_in, const int* in_sizes, int n_in,
                              void* d_out, int out_size) {
    // Resolve inputs by element count (robust to optional num_nodes scalar).
    int iEI = -1, iEA = -1, iW1 = -1, iW2 = -1, iB1 = -1, iB2 = -1;
    for (int i = 0; i < n_in; ++i) {
        int s = in_sizes[i];
        if (s == 3200000) iEI = i;                    // edge_index [2, E]
        else if (s == 102400000) iEA = i;             // edge_attr [E, 64]
        else if (s == 8192) { if (iW1 < 0) iW1 = i; else iW2 = i; }  // W1 then W2
        else if (s == 128) iB1 = i;                   // b1
        else if (s == 64)  iB2 = i;                   // b2
    }
    const int E = in_sizes[iEI] / 2;

    const int smem_bytes = (16576 + 64 * 257) * 4;    // 132096
    cudaFuncSetAttribute(mlp_kernel, cudaFuncAttributeMaxDynamicSharedMemorySize,
                         smem_bytes);

    detect_kernel<<<1, 32>>>((const int*)d_in[iEI]);
    zero_kernel<<<(N_NODES * D_FEAT / 4 + 255) / 256, 256>>>();

    long long total = (long long)E * 16;
    scatter_kernel<<<(int)((total + 255) / 256), 256>>>(
        (const float4*)d_in[iEA], d_in[iEI], E);

    mlp_kernel<<<(N_NODES + 255) / 256, 256, smem_bytes>>>(
        (const float*)d_in[iW1], (const float*)d_in[iB1],
        (const float*)d_in[iW2], (const float*)d_in[iB2], (float*)d_out);
}

// round 4
// speedup vs baseline: 1.0407x; 1.0407x over previous
#include <cuda_runtime.h>
#include <cstdint>

#define N_NODES 100000
#define D_FEAT 64
#define H_DIM 128
#define MLP_T 352                 // 11 warps
#define SF_PITCH 353              // odd pitch: conflict-free transpose writes

typedef unsigned long long ull;

__device__ float g_flow[N_NODES * D_FEAT];
__device__ int g_is64;

// ---------------- packed f32x2 helpers ----------------
__device__ __forceinline__ ull f2pack(float lo, float hi) {
    ull r; asm("mov.b64 %0,{%1,%2};" : "=l"(r) : "f"(lo), "f"(hi)); return r;
}
__device__ __forceinline__ ull f2splat(float x) {
    ull r; asm("mov.b64 %0,{%1,%1};" : "=l"(r) : "f"(x)); return r;
}
__device__ __forceinline__ void f2unpack(ull v, float& lo, float& hi) {
    asm("mov.b64 {%0,%1},%2;" : "=f"(lo), "=f"(hi) : "l"(v));
}
__device__ __forceinline__ ull f2fma(ull a, ull b, ull c) {
    ull d; asm("fma.rn.f32x2 %0,%1,%2,%3;" : "=l"(d) : "l"(a), "l"(b), "l"(c));
    return d;
}

// ---------------------------------------------------------------------------
// int64 vs int32 edge_index detection (node ids < 2^31 -> high words all 0)
// ---------------------------------------------------------------------------
__global__ void detect_kernel(const int* __restrict__ ei) {
    if (threadIdx.x == 0 && blockIdx.x == 0) {
        int ok = 1;
        for (int i = 0; i < 512; ++i)
            if (ei[2 * i + 1] != 0) { ok = 0; break; }
        g_is64 = ok;
    }
}

__global__ void zero_kernel() {
    int i = blockIdx.x * blockDim.x + threadIdx.x;
    const int n = (N_NODES * D_FEAT) / 4;
    if (i < n)
        reinterpret_cast<float4*>(g_flow)[i] = make_float4(0.f, 0.f, 0.f, 0.f);
}

// ---------------------------------------------------------------------------
// Scatter: 16 threads/edge, one float4 each, red.global.add.v4.f32 to both
// endpoints. edge_attr read with ld.global.cs (streaming / evict-first) so
// the 410MB stream doesn't evict the hot 25.6MB flow region out of L2.
// ---------------------------------------------------------------------------
__global__ void scatter_kernel(const float4* __restrict__ ea,
                               const void* __restrict__ eidx, int E) {
    long long tid = (long long)blockIdx.x * blockDim.x + threadIdx.x;
    int e = (int)(tid >> 4);
    int q = (int)(tid & 15);
    if (e >= E) return;

    long long a, b;
    if (g_is64) {
        const long long* x = (const long long*)eidx;
        a = x[e];
        b = x[E + e];
    } else {
        const int* x = (const int*)eidx;
        a = (long long)x[e];
        b = (long long)x[E + e];
    }

    float4 v = __ldcs(ea + (long long)e * 16 + q);

    float* p0 = &g_flow[a * 64 + q * 4];
    float* p1 = &g_flow[b * 64 + q * 4];
    asm volatile("red.global.add.v4.f32 [%0], {%1,%2,%3,%4};"
                 :: "l"(p0), "f"(v.x), "f"(v.y), "f"(v.z), "f"(v.w) : "memory");
    asm volatile("red.global.add.v4.f32 [%0], {%1,%2,%3,%4};"
                 :: "l"(p1), "f"(v.x), "f"(v.y), "f"(v.z), "f"(v.w) : "memory");
}

// ---------------------------------------------------------------------------
// Fused MLP with packed fma.rn.f32x2 (FFMA2).
// One node per thread, 352 threads/block (11 warps).
// Phase 1 vectorized over hidden pairs (splat fl[d], 8 hidden per group).
// Phase 2 vectorized over output pairs (splat h_k, W2 pairs contiguous).
// SMEM (floats): sW1[8192] | sW2[8192] | sb1[128] | sb2[64] | sF[64*353]
// ---------------------------------------------------------------------------
__global__ __launch_bounds__(MLP_T, 1) void mlp_kernel(
    const float* __restrict__ W1, const float* __restrict__ b1,
    const float* __restrict__ W2, const float* __restrict__ b2,
    float* __restrict__ out) {
    extern __shared__ float sm[];
    float* sW1 = sm;             // 8192
    float* sW2 = sm + 8192;      // 8192
    float* sb1 = sm + 16384;     // 128
    float* sb2 = sm + 16512;     // 64
    float* sF  = sm + 16576;     // 64 * 353

    const int tid = threadIdx.x;
    const int node0 = blockIdx.x * MLP_T;
    const int nNodes = min(MLP_T, N_NODES - node0);

    for (int i = tid; i < 8192; i += MLP_T) sW1[i] = W1[i];
    for (int i = tid; i < 8192; i += MLP_T) sW2[i] = W2[i];
    if (tid < 128) sb1[tid] = b1[tid];
    if (tid < 64)  sb2[tid] = b2[tid];
    // Coalesced flow tile load, stored transposed sF[d][n] (odd pitch).
    for (int i = tid; i < nNodes * 64; i += MLP_T) {
        int n = i >> 6, d = i & 63;
        sF[d * SF_PITCH + n] = g_flow[(long long)(node0 + n) * 64 + d];
    }
    __syncthreads();

    const bool active = (tid < nNodes);
    float fl[64];
    #pragma unroll
    for (int d = 0; d < 64; ++d) fl[d] = active ? sF[d * SF_PITCH + tid] : 0.f;

    ull acc[32];
    #pragma unroll
    for (int o = 0; o < 32; ++o) acc[o] = 0ull;

    #pragma unroll 1
    for (int g = 0; g < 16; ++g) {
        const int j0 = g * 8;
        // ---- phase 1: 8 hidden units as 4 packed accumulators ----
        ull h01 = f2pack(sb1[j0 + 0], sb1[j0 + 1]);
        ull h23 = f2pack(sb1[j0 + 2], sb1[j0 + 3]);
        ull h45 = f2pack(sb1[j0 + 4], sb1[j0 + 5]);
        ull h67 = f2pack(sb1[j0 + 6], sb1[j0 + 7]);
        #pragma unroll
        for (int d = 0; d < 64; ++d) {
            ull fd2 = f2splat(fl[d]);
            const ulonglong2* wp =
                reinterpret_cast<const ulonglong2*>(&sW1[d * 128 + j0]);
            ulonglong2 wa = wp[0];
            ulonglong2 wb = wp[1];
            h01 = f2fma(fd2, wa.x, h01);
            h23 = f2fma(fd2, wa.y, h23);
            h45 = f2fma(fd2, wb.x, h45);
            h67 = f2fma(fd2, wb.y, h67);
        }
        float hs[8];
        f2unpack(h01, hs[0], hs[1]);
        f2unpack(h23, hs[2], hs[3]);
        f2unpack(h45, hs[4], hs[5]);
        f2unpack(h67, hs[6], hs[7]);
        #pragma unroll
        for (int k = 0; k < 8; ++k) hs[k] = fmaxf(hs[k], 0.f);

        // ---- phase 2: accumulate into 32 packed output pairs ----
        #pragma unroll
        for (int k = 0; k < 8; ++k) {
            ull hk2 = f2splat(hs[k]);
            const ulonglong2* w2p =
                reinterpret_cast<const ulonglong2*>(&sW2[(j0 + k) * 64]);
            #pragma unroll
            for (int o = 0; o < 16; ++o) {
                ulonglong2 w = w2p[o];
                acc[2 * o]     = f2fma(hk2, w.x, acc[2 * o]);
                acc[2 * o + 1] = f2fma(hk2, w.y, acc[2 * o + 1]);
            }
        }
    }

    // Column-private writeback into sF, then coalesced transposed store.
    if (active) {
        #pragma unroll
        for (int o = 0; o < 32; ++o) {
            float a0, a1;
            f2unpack(acc[o], a0, a1);
            sF[(2 * o) * SF_PITCH + tid]     = a0 + sb2[2 * o];
            sF[(2 * o + 1) * SF_PITCH + tid] = a1 + sb2[2 * o + 1];
        }
    }
    __syncthreads();
    for (int i = tid; i < nNodes * 64; i += MLP_T) {
        int n = i >> 6, d = i & 63;
        out[(long long)(node0 + n) * 64 + d] = sF[d * SF_PITCH + n];
    }
}

// ---------------------------------------------------------------------------
// Launch
// ---------------------------------------------------------------------------
extern "C" void kernel_launch(void* const* d_in, const int* in_sizes, int n_in,
                              void* d_out, int out_size) {
    int iEI = -1, iEA = -1, iW1 = -1, iW2 = -1, iB1 = -1, iB2 = -1;
    for (int i = 0; i < n_in; ++i) {
        int s = in_sizes[i];
        if (s == 3200000) iEI = i;
        else if (s == 102400000) iEA = i;
        else if (s == 8192) { if (iW1 < 0) iW1 = i; else iW2 = i; }
        else if (s == 128) iB1 = i;
        else if (s == 64)  iB2 = i;
    }
    const int E = in_sizes[iEI] / 2;

    const int smem_bytes = (16576 + 64 * SF_PITCH) * 4;   // 156,672 B
    cudaFuncSetAttribute(mlp_kernel, cudaFuncAttributeMaxDynamicSharedMemorySize,
                         smem_bytes);

    detect_kernel<<<1, 32>>>((const int*)d_in[iEI]);
    zero_kernel<<<(N_NODES * D_FEAT / 4 + 255) / 256, 256>>>();

    long long total = (long long)E * 16;
    scatter_kernel<<<(int)((total + 255) / 256), 256>>>(
        (const float4*)d_in[iEA], d_in[iEI], E);

    mlp_kernel<<<(N_NODES + MLP_T - 1) / MLP_T, MLP_T, smem_bytes>>>(
        (const float*)d_in[iW1], (const float*)d_in[iB1],
        (const float*)d_in[iW2], (const float*)d_in[iB2], (float*)d_out);
}